// round 1
// baseline (speedup 1.0000x reference)
#include <cuda_runtime.h>
#include <cstddef>

#define NN 50000
#define DD 128
#define BM 128
#define BK 16
#define TM 8
#define TN 8

// Scratch (allocation-free rule: device globals)
__device__ float g_Wh_chem[NN * DD];
__device__ float g_Wh_elec[NN * DD];
__device__ float g_h[NN * DD];

// C[M,128] = A[M,128] @ W^T + bias (+ extra). blockIdx.y selects (W0,b0,C0) vs (W1,b1,C1).
// On y==0, optionally zero zbuf over the same row range (used to clear g_h during the dual GEMM).
__global__ __launch_bounds__(256, 2)
void gemm128_kernel(const float* __restrict__ A,
                    const float* __restrict__ W0, const float* __restrict__ b0,
                    float* __restrict__ C0,
                    const float* __restrict__ W1, const float* __restrict__ b1,
                    float* __restrict__ C1,
                    const float* __restrict__ extra,
                    float* __restrict__ zbuf,
                    int M)
{
    __shared__ float As[BK][BM];   // As[k][m]
    __shared__ float Bs[BK][DD];   // Bs[k][j] = W[j][k]

    const float* W    = W0;
    const float* bias = b0;
    float*       C    = C0;
    const float* ex   = extra;
    float*       zb   = zbuf;
    if (blockIdx.y == 1) { W = W1; bias = b1; C = C1; ex = nullptr; zb = nullptr; }

    const int tid  = threadIdx.x;
    const int bm   = blockIdx.x * BM;
    const int colg = tid & 15;          // 0..15
    const int rowg = tid >> 4;          // 0..15
    const int crow = rowg * TM;         // local row base
    const int ccol = colg * TN;         // column base

    float acc[TM][TN];
    #pragma unroll
    for (int i = 0; i < TM; i++)
        #pragma unroll
        for (int j = 0; j < TN; j++) acc[i][j] = 0.0f;

    for (int k0 = 0; k0 < DD; k0 += BK) {
        // Load A tile (128 rows x 16 k) and B tile (W^T: 16 k x 128 j).
        // 512 float4 each; 2 per thread.
        #pragma unroll
        for (int i = 0; i < 2; i++) {
            int g   = tid + 256 * i;
            int row = g >> 2;           // 0..127
            int q   = g & 3;            // float4 slot within the 16-wide k chunk
            // A (guarded, transpose into As[k][m])
            float4 va = make_float4(0.f, 0.f, 0.f, 0.f);
            int ar = bm + row;
            if (ar < M) va = *(const float4*)(A + (size_t)ar * DD + k0 + q * 4);
            As[q * 4 + 0][row] = va.x;
            As[q * 4 + 1][row] = va.y;
            As[q * 4 + 2][row] = va.z;
            As[q * 4 + 3][row] = va.w;
            // W (row = j here), transpose into Bs[k][j]
            float4 vb = *(const float4*)(W + (size_t)row * DD + k0 + q * 4);
            Bs[q * 4 + 0][row] = vb.x;
            Bs[q * 4 + 1][row] = vb.y;
            Bs[q * 4 + 2][row] = vb.z;
            Bs[q * 4 + 3][row] = vb.w;
        }
        __syncthreads();

        #pragma unroll
        for (int kk = 0; kk < BK; kk++) {
            float a[TM], b[TN];
            *(float4*)(a)     = *(const float4*)&As[kk][crow];
            *(float4*)(a + 4) = *(const float4*)&As[kk][crow + 4];
            *(float4*)(b)     = *(const float4*)&Bs[kk][ccol];
            *(float4*)(b + 4) = *(const float4*)&Bs[kk][ccol + 4];
            #pragma unroll
            for (int i = 0; i < TM; i++)
                #pragma unroll
                for (int j = 0; j < TN; j++)
                    acc[i][j] = fmaf(a[i], b[j], acc[i][j]);
        }
        __syncthreads();
    }

    // Epilogue
    float4 blo = *(const float4*)(bias + ccol);
    float4 bhi = *(const float4*)(bias + ccol + 4);
    #pragma unroll
    for (int i = 0; i < TM; i++) {
        int r = bm + crow + i;
        if (r >= M) continue;
        float4 o0, o1;
        o0.x = acc[i][0] + blo.x; o0.y = acc[i][1] + blo.y;
        o0.z = acc[i][2] + blo.z; o0.w = acc[i][3] + blo.w;
        o1.x = acc[i][4] + bhi.x; o1.y = acc[i][5] + bhi.y;
        o1.z = acc[i][6] + bhi.z; o1.w = acc[i][7] + bhi.w;
        if (ex) {
            float4 e0 = *(const float4*)(ex + (size_t)r * DD + ccol);
            float4 e1 = *(const float4*)(ex + (size_t)r * DD + ccol + 4);
            o0.x += e0.x; o0.y += e0.y; o0.z += e0.z; o0.w += e0.w;
            o1.x += e1.x; o1.y += e1.y; o1.z += e1.z; o1.w += e1.w;
        }
        *(float4*)(C + (size_t)r * DD + ccol)     = o0;
        *(float4*)(C + (size_t)r * DD + ccol + 4) = o1;
        if (zb) {
            float4 z = make_float4(0.f, 0.f, 0.f, 0.f);
            *(float4*)(zb + (size_t)r * DD + ccol)     = z;
            *(float4*)(zb + (size_t)r * DD + ccol + 4) = z;
        }
    }
}

// One warp per edge: gather 128 floats of Wh[src] (float4/lane), vector-reduce into g_h[dst].
__global__ __launch_bounds__(256)
void scatter_kernel(const int* __restrict__ src, const int* __restrict__ dst,
                    const float* __restrict__ Wh, int nE)
{
    int warp = (int)((blockIdx.x * (unsigned)blockDim.x + threadIdx.x) >> 5);
    int lane = threadIdx.x & 31;
    if (warp >= nE) return;
    int s = __ldg(src + warp);
    int d = __ldg(dst + warp);
    float4 v = __ldg((const float4*)(Wh + (size_t)s * DD) + lane);
    float* out = g_h + (size_t)d * DD + (size_t)lane * 4;
    asm volatile("red.global.add.v4.f32 [%0], {%1, %2, %3, %4};"
                 :: "l"(out), "f"(v.x), "f"(v.y), "f"(v.z), "f"(v.w)
                 : "memory");
}

extern "C" void kernel_launch(void* const* d_in, const int* in_sizes, int n_in,
                              void* d_out, int out_size)
{
    const float* feats   = (const float*)d_in[0];
    const float* W_chem  = (const float*)d_in[1];
    const float* b_chem  = (const float*)d_in[2];
    const float* W_elec  = (const float*)d_in[3];
    const float* b_elec  = (const float*)d_in[4];
    const float* W_out   = (const float*)d_in[5];
    const float* b_out   = (const float*)d_in[6];
    const int*   src_ch  = (const int*)d_in[7];
    const int*   dst_ch  = (const int*)d_in[8];
    const int*   src_el  = (const int*)d_in[9];
    const int*   dst_el  = (const int*)d_in[10];
    float*       out     = (float*)d_out;

    const int M       = in_sizes[0] / DD;   // 50000
    const int nE_chem = in_sizes[7];        // 500000
    const int nE_elec = in_sizes[9];        // 500000

    float *wh_chem, *wh_elec, *hbuf;
    cudaGetSymbolAddress((void**)&wh_chem, g_Wh_chem);
    cudaGetSymbolAddress((void**)&wh_elec, g_Wh_elec);
    cudaGetSymbolAddress((void**)&hbuf,    g_h);

    const int mblocks = (M + BM - 1) / BM;  // 391

    // K1: dual GEMM — y==0: Wh_chem (+ zero g_h), y==1: Wh_elec
    gemm128_kernel<<<dim3(mblocks, 2), 256>>>(
        feats, W_chem, b_chem, wh_chem,
        W_elec, b_elec, wh_elec,
        /*extra=*/nullptr, /*zbuf=*/hbuf, M);

    // K2/K3: edge aggregation (vector L2 reductions)
    {
        int wpb = 256 / 32;
        int blk_c = (nE_chem + wpb - 1) / wpb;
        int blk_e = (nE_elec + wpb - 1) / wpb;
        scatter_kernel<<<blk_c, 256>>>(src_ch, dst_ch, wh_chem, nE_chem);
        scatter_kernel<<<blk_e, 256>>>(src_el, dst_el, wh_elec, nE_elec);
    }

    // K4: out = h @ W_out^T + b_out + Wh_elec
    gemm128_kernel<<<dim3(mblocks, 1), 256>>>(
        hbuf, W_out, b_out, out,
        /*W1*/nullptr, /*b1*/nullptr, /*C1*/nullptr,
        /*extra=*/wh_elec, /*zbuf=*/nullptr, M);
}

// round 2
// speedup vs baseline: 1.4883x; 1.4883x over previous
#include <cuda_runtime.h>
#include <cstdint>
#include <cstddef>

#define NN 50000
#define DD 128
#define BM 128
#define AS_STRIDE 36
#define BS_STRIDE 132

// Scratch (allocation-free rule: device globals)
__device__ float g_Wh_chem[NN * DD];
__device__ float g_Wh_elec[NN * DD];
__device__ float g_h[NN * DD];

__device__ __forceinline__ uint32_t f2tf32(float f) {
    uint32_t r;
    asm("cvt.rna.tf32.f32 %0, %1;" : "=r"(r) : "f"(f));
    return r;
}

__device__ __forceinline__ void mma_tf32(float c[4], const uint32_t a[4], const uint32_t b[2]) {
    asm volatile(
        "mma.sync.aligned.m16n8k8.row.col.f32.tf32.tf32.f32 "
        "{%0,%1,%2,%3}, {%4,%5,%6,%7}, {%8,%9}, {%0,%1,%2,%3};"
        : "+f"(c[0]), "+f"(c[1]), "+f"(c[2]), "+f"(c[3])
        : "r"(a[0]), "r"(a[1]), "r"(a[2]), "r"(a[3]), "r"(b[0]), "r"(b[1]));
}

// C[M,128] = A[M,128] @ W^T + bias (+ extra). blockIdx.y selects param set.
// y==0 optionally zeroes zbuf over the tile (used to clear g_h during K1).
__global__ __launch_bounds__(256, 2)
void gemm_tf32_kernel(const float* __restrict__ A,
                      const float* __restrict__ W0, const float* __restrict__ b0,
                      float* __restrict__ C0,
                      const float* __restrict__ W1, const float* __restrict__ b1,
                      float* __restrict__ C1,
                      const float* __restrict__ extra,
                      float* __restrict__ zbuf,
                      int M)
{
    __shared__ uint32_t As[BM][AS_STRIDE];   // As[m][k] tf32, padded
    __shared__ uint32_t Bs[32][BS_STRIDE];   // Bs[k][j] = W[j][k] tf32, padded

    const float* W    = W0;
    const float* bias = b0;
    float*       C    = C0;
    const float* ex   = extra;
    float*       zb   = zbuf;
    if (blockIdx.y == 1) { W = W1; bias = b1; C = C1; ex = nullptr; zb = nullptr; }

    const int tid  = threadIdx.x;
    const int lane = tid & 31;
    const int w    = tid >> 5;          // 8 warps
    const int wm   = w & 3;             // 4 m-warps
    const int wn   = w >> 2;            // 2 n-warps
    const int mw   = wm * 32;
    const int nw   = wn * 64;
    const int gid  = lane >> 2;         // 0..7
    const int tig  = lane & 3;          // 0..3
    const int bm   = blockIdx.x * BM;

    float c[2][8][4];
    #pragma unroll
    for (int mt = 0; mt < 2; mt++)
        #pragma unroll
        for (int nt = 0; nt < 8; nt++)
            #pragma unroll
            for (int q = 0; q < 4; q++) c[mt][nt][q] = 0.0f;

    for (int k0 = 0; k0 < DD; k0 += 32) {
        // Load A tile (128x32) and W tile (128 rows j x 32 k, transposed into Bs).
        // 1024 float4 each; 4 per thread.
        #pragma unroll
        for (int i = 0; i < 4; i++) {
            int g   = tid + 256 * i;
            int row = g >> 3;           // 0..127
            int qc  = g & 7;            // float4 slot in 32-wide k chunk
            // A (guarded)
            float4 va = make_float4(0.f, 0.f, 0.f, 0.f);
            int ar = bm + row;
            if (ar < M) va = *(const float4*)(A + (size_t)ar * DD + k0 + qc * 4);
            As[row][qc * 4 + 0] = f2tf32(va.x);
            As[row][qc * 4 + 1] = f2tf32(va.y);
            As[row][qc * 4 + 2] = f2tf32(va.z);
            As[row][qc * 4 + 3] = f2tf32(va.w);
            // W row j=row, cols k0+qc*4.. -> transpose into Bs[k][j]
            float4 vb = *(const float4*)(W + (size_t)row * DD + k0 + qc * 4);
            Bs[qc * 4 + 0][row] = f2tf32(vb.x);
            Bs[qc * 4 + 1][row] = f2tf32(vb.y);
            Bs[qc * 4 + 2][row] = f2tf32(vb.z);
            Bs[qc * 4 + 3][row] = f2tf32(vb.w);
        }
        __syncthreads();

        #pragma unroll
        for (int ks = 0; ks < 4; ks++) {
            const int k8 = ks * 8;
            uint32_t a[2][4], b[8][2];
            #pragma unroll
            for (int mt = 0; mt < 2; mt++) {
                int r0 = mw + mt * 16 + gid;
                a[mt][0] = As[r0][k8 + tig];
                a[mt][1] = As[r0 + 8][k8 + tig];
                a[mt][2] = As[r0][k8 + tig + 4];
                a[mt][3] = As[r0 + 8][k8 + tig + 4];
            }
            #pragma unroll
            for (int nt = 0; nt < 8; nt++) {
                int cc = nw + nt * 8 + gid;
                b[nt][0] = Bs[k8 + tig][cc];
                b[nt][1] = Bs[k8 + tig + 4][cc];
            }
            #pragma unroll
            for (int mt = 0; mt < 2; mt++)
                #pragma unroll
                for (int nt = 0; nt < 8; nt++)
                    mma_tf32(c[mt][nt], a[mt], b[nt]);
        }
        __syncthreads();
    }

    // Epilogue: c0/c1 -> (row gid, cols 2*tig, 2*tig+1); c2/c3 -> row gid+8
    #pragma unroll
    for (int mt = 0; mt < 2; mt++) {
        #pragma unroll
        for (int half = 0; half < 2; half++) {
            int r = bm + mw + mt * 16 + gid + half * 8;
            if (r >= M) continue;
            #pragma unroll
            for (int nt = 0; nt < 8; nt++) {
                int col = nw + nt * 8 + tig * 2;
                float2 o;
                o.x = c[mt][nt][half * 2 + 0] + bias[col];
                o.y = c[mt][nt][half * 2 + 1] + bias[col + 1];
                if (ex) {
                    float2 e = *(const float2*)(ex + (size_t)r * DD + col);
                    o.x += e.x; o.y += e.y;
                }
                *(float2*)(C + (size_t)r * DD + col) = o;
                if (zb) *(float2*)(zb + (size_t)r * DD + col) = make_float2(0.f, 0.f);
            }
        }
    }
}

// One warp per edge: gather 128 floats of Wh[src] (float4/lane), vector-reduce into g_h[dst].
__global__ __launch_bounds__(256)
void scatter_kernel(const int* __restrict__ src, const int* __restrict__ dst,
                    const float* __restrict__ Wh, int nE)
{
    int warp = (int)((blockIdx.x * (unsigned)blockDim.x + threadIdx.x) >> 5);
    int lane = threadIdx.x & 31;
    if (warp >= nE) return;
    int s = __ldg(src + warp);
    int d = __ldg(dst + warp);
    float4 v = __ldg((const float4*)(Wh + (size_t)s * DD) + lane);
    float* out = g_h + (size_t)d * DD + (size_t)lane * 4;
    asm volatile("red.global.add.v4.f32 [%0], {%1, %2, %3, %4};"
                 :: "l"(out), "f"(v.x), "f"(v.y), "f"(v.z), "f"(v.w)
                 : "memory");
}

extern "C" void kernel_launch(void* const* d_in, const int* in_sizes, int n_in,
                              void* d_out, int out_size)
{
    const float* feats   = (const float*)d_in[0];
    const float* W_chem  = (const float*)d_in[1];
    const float* b_chem  = (const float*)d_in[2];
    const float* W_elec  = (const float*)d_in[3];
    const float* b_elec  = (const float*)d_in[4];
    const float* W_out   = (const float*)d_in[5];
    const float* b_out   = (const float*)d_in[6];
    const int*   src_ch  = (const int*)d_in[7];
    const int*   dst_ch  = (const int*)d_in[8];
    const int*   src_el  = (const int*)d_in[9];
    const int*   dst_el  = (const int*)d_in[10];
    float*       out     = (float*)d_out;

    const int M       = in_sizes[0] / DD;   // 50000
    const int nE_chem = in_sizes[7];        // 500000
    const int nE_elec = in_sizes[9];        // 500000

    float *wh_chem, *wh_elec, *hbuf;
    cudaGetSymbolAddress((void**)&wh_chem, g_Wh_chem);
    cudaGetSymbolAddress((void**)&wh_elec, g_Wh_elec);
    cudaGetSymbolAddress((void**)&hbuf,    g_h);

    const int mblocks = (M + BM - 1) / BM;  // 391

    // K1: dual GEMM — y==0: Wh_chem (+ zero g_h), y==1: Wh_elec
    gemm_tf32_kernel<<<dim3(mblocks, 2), 256>>>(
        feats, W_chem, b_chem, wh_chem,
        W_elec, b_elec, wh_elec,
        /*extra=*/nullptr, /*zbuf=*/hbuf, M);

    // K2/K3: edge aggregation (vector L2 reductions)
    {
        int wpb = 256 / 32;
        int blk_c = (nE_chem + wpb - 1) / wpb;
        int blk_e = (nE_elec + wpb - 1) / wpb;
        scatter_kernel<<<blk_c, 256>>>(src_ch, dst_ch, wh_chem, nE_chem);
        scatter_kernel<<<blk_e, 256>>>(src_el, dst_el, wh_elec, nE_elec);
    }

    // K4: out = h @ W_out^T + b_out + Wh_elec
    gemm_tf32_kernel<<<dim3(mblocks, 1), 256>>>(
        hbuf, W_out, b_out, out,
        /*W1*/nullptr, /*b1*/nullptr, /*C1*/nullptr,
        /*extra=*/wh_elec, /*zbuf=*/nullptr, M);
}

// round 3
// speedup vs baseline: 1.5633x; 1.0504x over previous
#include <cuda_runtime.h>
#include <cstdint>
#include <cstddef>

#define NN 50000
#define DD 128
#define BM 128
#define ST 36   // smem row stride (words): gid*36+tig is injective mod 32 -> conflict-free

// Scratch (allocation-free rule: device globals)
__device__ float g_Wh_chem[NN * DD];
__device__ float g_Wh_elec[NN * DD];
__device__ float g_h[NN * DD];

__device__ __forceinline__ uint32_t f2tf32(float f) {
    uint32_t r;
    asm("cvt.rna.tf32.f32 %0, %1;" : "=r"(r) : "f"(f));
    return r;
}

__device__ __forceinline__ void mma_tf32(float c[4], const uint32_t a[4], const uint32_t b[2]) {
    asm volatile(
        "mma.sync.aligned.m16n8k8.row.col.f32.tf32.tf32.f32 "
        "{%0,%1,%2,%3}, {%4,%5,%6,%7}, {%8,%9}, {%0,%1,%2,%3};"
        : "+f"(c[0]), "+f"(c[1]), "+f"(c[2]), "+f"(c[3])
        : "r"(a[0]), "r"(a[1]), "r"(a[2]), "r"(a[3]), "r"(b[0]), "r"(b[1]));
}

// Dynamic smem layout: As[2][128][ST] | Ws[4][128][ST]
#define AS_WORDS (2 * 128 * ST)
#define WS_WORDS (4 * 128 * ST)
#define SMEM_BYTES ((AS_WORDS + WS_WORDS) * 4)

// C[M,128] = A[M,128] @ W^T + bias (+ extra). blockIdx.y selects param set.
// y==0 optionally zeroes zbuf over the tile (clears g_h during K1).
__global__ __launch_bounds__(256, 2)
void gemm_tf32_kernel(const float* __restrict__ A,
                      const float* __restrict__ W0, const float* __restrict__ b0,
                      float* __restrict__ C0,
                      const float* __restrict__ W1, const float* __restrict__ b1,
                      float* __restrict__ C1,
                      const float* __restrict__ extra,
                      float* __restrict__ zbuf,
                      int M)
{
    extern __shared__ uint32_t smem[];
    uint32_t* As = smem;                 // As[buf][row][k]  buf*128*ST + row*ST + k
    uint32_t* Ws = smem + AS_WORDS;      // Ws[c][j][k]      c*128*ST + j*ST + k

    const float* W    = W0;
    const float* bias = b0;
    float*       C    = C0;
    const float* ex   = extra;
    float*       zb   = zbuf;
    if (blockIdx.y == 1) { W = W1; bias = b1; C = C1; ex = nullptr; zb = nullptr; }

    const int tid  = threadIdx.x;
    const int lane = tid & 31;
    const int w    = tid >> 5;          // 8 warps
    const int wm   = w & 3;             // 4 m-warps
    const int wn   = w >> 2;            // 2 n-warps
    const int mw   = wm * 32;
    const int nw   = wn * 64;
    const int gid  = lane >> 2;         // 0..7
    const int tig  = lane & 3;          // 0..3
    const int bm   = blockIdx.x * BM;

    // ---- Prologue: load ALL of W (128x128) into Ws[4 chunks], row-major, tf32 ----
    #pragma unroll
    for (int i = 0; i < 16; i++) {
        int g   = tid + 256 * i;        // 0..4095
        int c   = g >> 10;              // chunk 0..3
        int row = (g >> 3) & 127;       // j
        int qc  = g & 7;                // float4 slot in 32-wide k chunk
        float4 vb = *(const float4*)(W + (size_t)row * DD + c * 32 + qc * 4);
        uint4 sv;
        sv.x = f2tf32(vb.x); sv.y = f2tf32(vb.y);
        sv.z = f2tf32(vb.z); sv.w = f2tf32(vb.w);
        *(uint4*)&Ws[(size_t)c * 128 * ST + row * ST + qc * 4] = sv;
    }

    // ---- Load A chunk 0 ----
    float4 av[4];
    #pragma unroll
    for (int i = 0; i < 4; i++) {
        int g   = tid + 256 * i;
        int row = g >> 3;
        int qc  = g & 7;
        int ar  = bm + row;
        av[i] = make_float4(0.f, 0.f, 0.f, 0.f);
        if (ar < M) av[i] = *(const float4*)(A + (size_t)ar * DD + qc * 4);
    }
    #pragma unroll
    for (int i = 0; i < 4; i++) {
        int g   = tid + 256 * i;
        int row = g >> 3;
        int qc  = g & 7;
        uint4 sv;
        sv.x = f2tf32(av[i].x); sv.y = f2tf32(av[i].y);
        sv.z = f2tf32(av[i].z); sv.w = f2tf32(av[i].w);
        *(uint4*)&As[row * ST + qc * 4] = sv;
    }
    __syncthreads();

    float acc[2][8][4];
    #pragma unroll
    for (int mt = 0; mt < 2; mt++)
        #pragma unroll
        for (int nt = 0; nt < 8; nt++)
            #pragma unroll
            for (int q = 0; q < 4; q++) acc[mt][nt][q] = 0.0f;

    #pragma unroll
    for (int c = 0; c < 4; c++) {
        // Prefetch next A chunk into registers (overlaps with compute below)
        if (c < 3) {
            #pragma unroll
            for (int i = 0; i < 4; i++) {
                int g   = tid + 256 * i;
                int row = g >> 3;
                int qc  = g & 7;
                int ar  = bm + row;
                av[i] = make_float4(0.f, 0.f, 0.f, 0.f);
                if (ar < M) av[i] = *(const float4*)(A + (size_t)ar * DD + (c + 1) * 32 + qc * 4);
            }
        }

        const uint32_t* Ab = As + (size_t)(c & 1) * 128 * ST;
        const uint32_t* Wc = Ws + (size_t)c * 128 * ST;

        #pragma unroll
        for (int ks = 0; ks < 4; ks++) {
            const int k8 = ks * 8;
            uint32_t a[2][4], b[8][2];
            #pragma unroll
            for (int mt = 0; mt < 2; mt++) {
                int r0 = mw + mt * 16 + gid;
                a[mt][0] = Ab[r0 * ST + k8 + tig];
                a[mt][1] = Ab[(r0 + 8) * ST + k8 + tig];
                a[mt][2] = Ab[r0 * ST + k8 + tig + 4];
                a[mt][3] = Ab[(r0 + 8) * ST + k8 + tig + 4];
            }
            #pragma unroll
            for (int nt = 0; nt < 8; nt++) {
                int cc = nw + nt * 8 + gid;
                b[nt][0] = Wc[cc * ST + k8 + tig];
                b[nt][1] = Wc[cc * ST + k8 + tig + 4];
            }
            #pragma unroll
            for (int mt = 0; mt < 2; mt++)
                #pragma unroll
                for (int nt = 0; nt < 8; nt++)
                    mma_tf32(acc[mt][nt], a[mt], b[nt]);
        }

        if (c < 3) {
            uint32_t* Anext = As + (size_t)((c + 1) & 1) * 128 * ST;
            #pragma unroll
            for (int i = 0; i < 4; i++) {
                int g   = tid + 256 * i;
                int row = g >> 3;
                int qc  = g & 7;
                uint4 sv;
                sv.x = f2tf32(av[i].x); sv.y = f2tf32(av[i].y);
                sv.z = f2tf32(av[i].z); sv.w = f2tf32(av[i].w);
                *(uint4*)&Anext[row * ST + qc * 4] = sv;
            }
            __syncthreads();
        }
    }

    // Epilogue: (mt,half) row = mw + mt*16 + gid + half*8; cols nw + nt*8 + tig*2
    #pragma unroll
    for (int mt = 0; mt < 2; mt++) {
        #pragma unroll
        for (int half = 0; half < 2; half++) {
            int r = bm + mw + mt * 16 + gid + half * 8;
            if (r >= M) continue;
            #pragma unroll
            for (int nt = 0; nt < 8; nt++) {
                int col = nw + nt * 8 + tig * 2;
                float2 o;
                o.x = acc[mt][nt][half * 2 + 0] + bias[col];
                o.y = acc[mt][nt][half * 2 + 1] + bias[col + 1];
                if (ex) {
                    float2 e = *(const float2*)(ex + (size_t)r * DD + col);
                    o.x += e.x; o.y += e.y;
                }
                *(float2*)(C + (size_t)r * DD + col) = o;
                if (zb) *(float2*)(zb + (size_t)r * DD + col) = make_float2(0.f, 0.f);
            }
        }
    }
}

// Fused dual-etype scatter: one warp per edge, vector L2 reduction into g_h[dst].
__global__ __launch_bounds__(256)
void scatter2_kernel(const int* __restrict__ src_c, const int* __restrict__ dst_c,
                     const float* __restrict__ Wh_c,
                     const int* __restrict__ src_e, const int* __restrict__ dst_e,
                     const float* __restrict__ Wh_e,
                     int nC, int nTot)
{
    int warp = (int)((blockIdx.x * (unsigned)blockDim.x + threadIdx.x) >> 5);
    int lane = threadIdx.x & 31;
    if (warp >= nTot) return;
    const int* srcp; const int* dstp; const float* Wh; int e;
    if (warp < nC) { srcp = src_c; dstp = dst_c; Wh = Wh_c; e = warp; }
    else           { srcp = src_e; dstp = dst_e; Wh = Wh_e; e = warp - nC; }
    int s = __ldg(srcp + e);
    int d = __ldg(dstp + e);
    float4 v = __ldg((const float4*)(Wh + (size_t)s * DD) + lane);
    float* out = g_h + (size_t)d * DD + (size_t)lane * 4;
    asm volatile("red.global.add.v4.f32 [%0], {%1, %2, %3, %4};"
                 :: "l"(out), "f"(v.x), "f"(v.y), "f"(v.z), "f"(v.w)
                 : "memory");
}

extern "C" void kernel_launch(void* const* d_in, const int* in_sizes, int n_in,
                              void* d_out, int out_size)
{
    const float* feats   = (const float*)d_in[0];
    const float* W_chem  = (const float*)d_in[1];
    const float* b_chem  = (const float*)d_in[2];
    const float* W_elec  = (const float*)d_in[3];
    const float* b_elec  = (const float*)d_in[4];
    const float* W_out   = (const float*)d_in[5];
    const float* b_out   = (const float*)d_in[6];
    const int*   src_ch  = (const int*)d_in[7];
    const int*   dst_ch  = (const int*)d_in[8];
    const int*   src_el  = (const int*)d_in[9];
    const int*   dst_el  = (const int*)d_in[10];
    float*       out     = (float*)d_out;

    const int M       = in_sizes[0] / DD;   // 50000
    const int nE_chem = in_sizes[7];        // 500000
    const int nE_elec = in_sizes[9];        // 500000

    float *wh_chem, *wh_elec, *hbuf;
    cudaGetSymbolAddress((void**)&wh_chem, g_Wh_chem);
    cudaGetSymbolAddress((void**)&wh_elec, g_Wh_elec);
    cudaGetSymbolAddress((void**)&hbuf,    g_h);

    // Opt into large dynamic smem (idempotent; host-side, capture-legal)
    cudaFuncSetAttribute(gemm_tf32_kernel,
                         cudaFuncAttributeMaxDynamicSharedMemorySize, SMEM_BYTES);

    const int mblocks = (M + BM - 1) / BM;  // 391

    // K1: dual GEMM — y==0: Wh_chem (+ zero g_h), y==1: Wh_elec
    gemm_tf32_kernel<<<dim3(mblocks, 2), 256, SMEM_BYTES>>>(
        feats, W_chem, b_chem, wh_chem,
        W_elec, b_elec, wh_elec,
        /*extra=*/nullptr, /*zbuf=*/hbuf, M);

    // K2: fused edge aggregation (vector L2 reductions), both etypes
    {
        int nTot = nE_chem + nE_elec;
        int wpb  = 256 / 32;
        int blk  = (nTot + wpb - 1) / wpb;
        scatter2_kernel<<<blk, 256>>>(src_ch, dst_ch, wh_chem,
                                      src_el, dst_el, wh_elec,
                                      nE_chem, nTot);
    }

    // K3: out = h @ W_out^T + b_out + Wh_elec
    gemm_tf32_kernel<<<dim3(mblocks, 1), 256, SMEM_BYTES>>>(
        hbuf, W_out, b_out, out,
        /*W1*/nullptr, /*b1*/nullptr, /*C1*/nullptr,
        /*extra=*/wh_elec, /*zbuf=*/nullptr, M);
}

// round 4
// speedup vs baseline: 2.3102x; 1.4778x over previous
#include <cuda_runtime.h>
#include <cstdint>
#include <cstddef>

#define NN 50000
#define DD 128
#define BM 128
#define ST 36            // smem row stride (words): conflict-free fragment access
#define CHUNK 512
#define NCHUNK 98        // ceil(50000/512)
#define PADN (NCHUNK * CHUNK)   // 50176
#define RSN (NN + 1)
#define NE 500000

// ---- Scratch (allocation-free rule: device globals) ----
__device__ float g_Wh_chem[NN * DD];
__device__ float g_Wh_elec[NN * DD];
__device__ float g_h[NN * DD];
__device__ int   g_deg[2 * PADN];     // per-etype dst degree (memset 0 each call)
__device__ int   g_local[2 * PADN];   // within-chunk exclusive scan
__device__ int   g_ctot[2 * NCHUNK];  // per-chunk totals
__device__ int   g_coff[2 * NCHUNK];  // scanned chunk offsets
__device__ int   g_rs[2 * RSN];       // row starts (CSR)
__device__ int   g_cur[2 * NN];       // placement cursors
__device__ int   g_csr[2 * NE];       // CSR src lists

__device__ __forceinline__ uint32_t f2tf32(float f) {
    uint32_t r;
    asm("cvt.rna.tf32.f32 %0, %1;" : "=r"(r) : "f"(f));
    return r;
}

__device__ __forceinline__ void mma_tf32(float c[4], const uint32_t a[4], const uint32_t b[2]) {
    asm volatile(
        "mma.sync.aligned.m16n8k8.row.col.f32.tf32.tf32.f32 "
        "{%0,%1,%2,%3}, {%4,%5,%6,%7}, {%8,%9}, {%0,%1,%2,%3};"
        : "+f"(c[0]), "+f"(c[1]), "+f"(c[2]), "+f"(c[3])
        : "r"(a[0]), "r"(a[1]), "r"(a[2]), "r"(a[3]), "r"(b[0]), "r"(b[1]));
}

// Dynamic smem: As[2][128][ST] | Ws[4][128][ST]
#define AS_WORDS (2 * 128 * ST)
#define WS_WORDS (4 * 128 * ST)
#define SMEM_BYTES ((AS_WORDS + WS_WORDS) * 4)

// C[M,128] = A[M,128] @ W^T + bias (+ extra). blockIdx.y selects param set.
__global__ __launch_bounds__(256, 2)
void gemm_tf32_kernel(const float* __restrict__ A,
                      const float* __restrict__ W0, const float* __restrict__ b0,
                      float* __restrict__ C0,
                      const float* __restrict__ W1, const float* __restrict__ b1,
                      float* __restrict__ C1,
                      const float* __restrict__ extra,
                      int M)
{
    extern __shared__ uint32_t smem[];
    uint32_t* As = smem;
    uint32_t* Ws = smem + AS_WORDS;

    const float* W    = W0;
    const float* bias = b0;
    float*       C    = C0;
    const float* ex   = extra;
    if (blockIdx.y == 1) { W = W1; bias = b1; C = C1; ex = nullptr; }

    const int tid  = threadIdx.x;
    const int lane = tid & 31;
    const int w    = tid >> 5;
    const int wm   = w & 3;
    const int wn   = w >> 2;
    const int mw   = wm * 32;
    const int nw   = wn * 64;
    const int gid  = lane >> 2;
    const int tig  = lane & 3;
    const int bm   = blockIdx.x * BM;

    // Prologue: all of W (128x128) into Ws, tf32, row-major
    #pragma unroll
    for (int i = 0; i < 16; i++) {
        int g   = tid + 256 * i;
        int c   = g >> 10;
        int row = (g >> 3) & 127;
        int qc  = g & 7;
        float4 vb = *(const float4*)(W + (size_t)row * DD + c * 32 + qc * 4);
        uint4 sv;
        sv.x = f2tf32(vb.x); sv.y = f2tf32(vb.y);
        sv.z = f2tf32(vb.z); sv.w = f2tf32(vb.w);
        *(uint4*)&Ws[(size_t)c * 128 * ST + row * ST + qc * 4] = sv;
    }

    float4 av[4];
    #pragma unroll
    for (int i = 0; i < 4; i++) {
        int g = tid + 256 * i, row = g >> 3, qc = g & 7, ar = bm + row;
        av[i] = make_float4(0.f, 0.f, 0.f, 0.f);
        if (ar < M) av[i] = *(const float4*)(A + (size_t)ar * DD + qc * 4);
    }
    #pragma unroll
    for (int i = 0; i < 4; i++) {
        int g = tid + 256 * i, row = g >> 3, qc = g & 7;
        uint4 sv;
        sv.x = f2tf32(av[i].x); sv.y = f2tf32(av[i].y);
        sv.z = f2tf32(av[i].z); sv.w = f2tf32(av[i].w);
        *(uint4*)&As[row * ST + qc * 4] = sv;
    }
    __syncthreads();

    float acc[2][8][4];
    #pragma unroll
    for (int mt = 0; mt < 2; mt++)
        #pragma unroll
        for (int nt = 0; nt < 8; nt++)
            #pragma unroll
            for (int q = 0; q < 4; q++) acc[mt][nt][q] = 0.0f;

    #pragma unroll
    for (int c = 0; c < 4; c++) {
        if (c < 3) {
            #pragma unroll
            for (int i = 0; i < 4; i++) {
                int g = tid + 256 * i, row = g >> 3, qc = g & 7, ar = bm + row;
                av[i] = make_float4(0.f, 0.f, 0.f, 0.f);
                if (ar < M) av[i] = *(const float4*)(A + (size_t)ar * DD + (c + 1) * 32 + qc * 4);
            }
        }
        const uint32_t* Ab = As + (size_t)(c & 1) * 128 * ST;
        const uint32_t* Wc = Ws + (size_t)c * 128 * ST;
        #pragma unroll
        for (int ks = 0; ks < 4; ks++) {
            const int k8 = ks * 8;
            uint32_t a[2][4], b[8][2];
            #pragma unroll
            for (int mt = 0; mt < 2; mt++) {
                int r0 = mw + mt * 16 + gid;
                a[mt][0] = Ab[r0 * ST + k8 + tig];
                a[mt][1] = Ab[(r0 + 8) * ST + k8 + tig];
                a[mt][2] = Ab[r0 * ST + k8 + tig + 4];
                a[mt][3] = Ab[(r0 + 8) * ST + k8 + tig + 4];
            }
            #pragma unroll
            for (int nt = 0; nt < 8; nt++) {
                int cc = nw + nt * 8 + gid;
                b[nt][0] = Wc[cc * ST + k8 + tig];
                b[nt][1] = Wc[cc * ST + k8 + tig + 4];
            }
            #pragma unroll
            for (int mt = 0; mt < 2; mt++)
                #pragma unroll
                for (int nt = 0; nt < 8; nt++)
                    mma_tf32(acc[mt][nt], a[mt], b[nt]);
        }
        if (c < 3) {
            uint32_t* Anext = As + (size_t)((c + 1) & 1) * 128 * ST;
            #pragma unroll
            for (int i = 0; i < 4; i++) {
                int g = tid + 256 * i, row = g >> 3, qc = g & 7;
                uint4 sv;
                sv.x = f2tf32(av[i].x); sv.y = f2tf32(av[i].y);
                sv.z = f2tf32(av[i].z); sv.w = f2tf32(av[i].w);
                *(uint4*)&Anext[row * ST + qc * 4] = sv;
            }
            __syncthreads();
        }
    }

    #pragma unroll
    for (int mt = 0; mt < 2; mt++) {
        #pragma unroll
        for (int half = 0; half < 2; half++) {
            int r = bm + mw + mt * 16 + gid + half * 8;
            if (r >= M) continue;
            #pragma unroll
            for (int nt = 0; nt < 8; nt++) {
                int col = nw + nt * 8 + tig * 2;
                float2 o;
                o.x = acc[mt][nt][half * 2 + 0] + bias[col];
                o.y = acc[mt][nt][half * 2 + 1] + bias[col + 1];
                if (ex) {
                    float2 e = *(const float2*)(ex + (size_t)r * DD + col);
                    o.x += e.x; o.y += e.y;
                }
                *(float2*)(C + (size_t)r * DD + col) = o;
            }
        }
    }
}

// ---- CSR build ----
__global__ __launch_bounds__(256)
void hist_kernel(const int* __restrict__ dst_c, const int* __restrict__ dst_e,
                 int nC, int nTot)
{
    int i = blockIdx.x * 256 + threadIdx.x;
    if (i >= nTot) return;
    int* cnt;
    if (i < nC) cnt = &g_deg[dst_c[i]];
    else        cnt = &g_deg[PADN + dst_e[i - nC]];
    asm volatile("red.global.add.u32 [%0], %1;" :: "l"(cnt), "r"(1) : "memory");
}

__global__ __launch_bounds__(512)
void scan_chunks_kernel(int N)
{
    const int et   = blockIdx.y;
    const int lane = threadIdx.x & 31;
    const int wid  = threadIdx.x >> 5;
    int n = blockIdx.x * CHUNK + threadIdx.x;
    int d = (n < N) ? g_deg[et * PADN + n] : 0;

    int incl = d;
    #pragma unroll
    for (int o = 1; o < 32; o <<= 1) {
        int t = __shfl_up_sync(0xffffffffu, incl, o);
        if (lane >= o) incl += t;
    }
    __shared__ int wtot[16];
    if (lane == 31) wtot[wid] = incl;
    __syncthreads();
    if (wid == 0) {
        int v = (lane < 16) ? wtot[lane] : 0;
        int wi = v;
        #pragma unroll
        for (int o = 1; o < 16; o <<= 1) {
            int t = __shfl_up_sync(0xffffffffu, wi, o);
            if (lane >= o) wi += t;
        }
        if (lane < 16) wtot[lane] = wi - v;   // exclusive warp bases
    }
    __syncthreads();
    int base = wtot[wid];
    if (n < N) g_local[et * PADN + n] = base + incl - d;
    if (wid == 15 && lane == 31) g_ctot[et * NCHUNK + blockIdx.x] = base + incl;
}

__global__ __launch_bounds__(64)
void scan_totals_kernel()
{
    const int et   = threadIdx.x >> 5;
    const int lane = threadIdx.x & 31;
    int carry = 0;
    for (int it = 0; it < (NCHUNK + 31) / 32; it++) {
        int idx = it * 32 + lane;
        int v = (idx < NCHUNK) ? g_ctot[et * NCHUNK + idx] : 0;
        int incl = v;
        #pragma unroll
        for (int o = 1; o < 32; o <<= 1) {
            int t = __shfl_up_sync(0xffffffffu, incl, o);
            if (lane >= o) incl += t;
        }
        if (idx < NCHUNK) g_coff[et * NCHUNK + idx] = carry + incl - v;
        carry += __shfl_sync(0xffffffffu, incl, 31);
    }
}

__global__ __launch_bounds__(256)
void rowstart_kernel(int N, int nEc, int nEe)
{
    int n = blockIdx.x * 256 + threadIdx.x;
    if (n > N) return;
    #pragma unroll
    for (int et = 0; et < 2; et++) {
        int v;
        if (n == N) v = et ? nEe : nEc;
        else v = g_coff[et * NCHUNK + (n >> 9)] + g_local[et * PADN + n];
        g_rs[et * RSN + n] = v;
        if (n < N) g_cur[et * NN + n] = v;
    }
}

__global__ __launch_bounds__(256)
void place_kernel(const int* __restrict__ src_c, const int* __restrict__ dst_c,
                  const int* __restrict__ src_e, const int* __restrict__ dst_e,
                  int nC, int nTot)
{
    int i = blockIdx.x * 256 + threadIdx.x;
    if (i >= nTot) return;
    if (i < nC) {
        int d = dst_c[i];
        int p = atomicAdd(&g_cur[d], 1);
        g_csr[p] = src_c[i];
    } else {
        int e = i - nC;
        int d = dst_e[e];
        int p = atomicAdd(&g_cur[NN + d], 1);
        g_csr[NE + p] = src_e[e];
    }
}

// ---- Gather aggregation: one warp per node, no atomics ----
__global__ __launch_bounds__(256)
void aggregate_kernel(int N)
{
    int warp = (int)((blockIdx.x * (unsigned)blockDim.x + threadIdx.x) >> 5);
    int lane = threadIdx.x & 31;
    if (warp >= N) return;

    float4 acc = make_float4(0.f, 0.f, 0.f, 0.f);

    #pragma unroll
    for (int et = 0; et < 2; et++) {
        const float* Wh  = et ? g_Wh_elec : g_Wh_chem;
        const int*   csr = g_csr + et * NE;
        int beg = __ldg(&g_rs[et * RSN + warp]);
        int end = __ldg(&g_rs[et * RSN + warp + 1]);
        int i = beg;
        for (; i + 1 < end; i += 2) {
            int s0 = __ldg(csr + i);
            int s1 = __ldg(csr + i + 1);
            float4 v0 = __ldg((const float4*)(Wh + (size_t)s0 * DD) + lane);
            float4 v1 = __ldg((const float4*)(Wh + (size_t)s1 * DD) + lane);
            acc.x += v0.x + v1.x; acc.y += v0.y + v1.y;
            acc.z += v0.z + v1.z; acc.w += v0.w + v1.w;
        }
        if (i < end) {
            int s0 = __ldg(csr + i);
            float4 v0 = __ldg((const float4*)(Wh + (size_t)s0 * DD) + lane);
            acc.x += v0.x; acc.y += v0.y; acc.z += v0.z; acc.w += v0.w;
        }
    }
    *((float4*)(g_h + (size_t)warp * DD) + lane) = acc;
}

extern "C" void kernel_launch(void* const* d_in, const int* in_sizes, int n_in,
                              void* d_out, int out_size)
{
    const float* feats   = (const float*)d_in[0];
    const float* W_chem  = (const float*)d_in[1];
    const float* b_chem  = (const float*)d_in[2];
    const float* W_elec  = (const float*)d_in[3];
    const float* b_elec  = (const float*)d_in[4];
    const float* W_out   = (const float*)d_in[5];
    const float* b_out   = (const float*)d_in[6];
    const int*   src_ch  = (const int*)d_in[7];
    const int*   dst_ch  = (const int*)d_in[8];
    const int*   src_el  = (const int*)d_in[9];
    const int*   dst_el  = (const int*)d_in[10];
    float*       out     = (float*)d_out;

    const int M       = in_sizes[0] / DD;   // 50000
    const int nE_chem = in_sizes[7];
    const int nE_elec = in_sizes[9];
    const int nTot    = nE_chem + nE_elec;

    float *wh_chem, *wh_elec, *hbuf;
    void  *degp;
    cudaGetSymbolAddress((void**)&wh_chem, g_Wh_chem);
    cudaGetSymbolAddress((void**)&wh_elec, g_Wh_elec);
    cudaGetSymbolAddress((void**)&hbuf,    g_h);
    cudaGetSymbolAddress(&degp,            g_deg);

    cudaFuncSetAttribute(gemm_tf32_kernel,
                         cudaFuncAttributeMaxDynamicSharedMemorySize, SMEM_BYTES);

    const int mblocks = (M + BM - 1) / BM;

    // K1: dual GEMM — Wh_chem & Wh_elec
    gemm_tf32_kernel<<<dim3(mblocks, 2), 256, SMEM_BYTES>>>(
        feats, W_chem, b_chem, wh_chem,
        W_elec, b_elec, wh_elec,
        /*extra=*/nullptr, M);

    // CSR build (independent of K1 results)
    cudaMemsetAsync(degp, 0, 2 * PADN * sizeof(int));
    hist_kernel<<<(nTot + 255) / 256, 256>>>(dst_ch, dst_el, nE_chem, nTot);
    scan_chunks_kernel<<<dim3(NCHUNK, 2), 512>>>(M);
    scan_totals_kernel<<<1, 64>>>();
    rowstart_kernel<<<(M + 256) / 256, 256>>>(M, nE_chem, nE_elec);
    place_kernel<<<(nTot + 255) / 256, 256>>>(src_ch, dst_ch, src_el, dst_el, nE_chem, nTot);

    // Gather aggregation (atomic-free)
    aggregate_kernel<<<(M * 32 + 255) / 256, 256>>>(M);

    // K4: out = h @ W_out^T + b_out + Wh_elec
    gemm_tf32_kernel<<<dim3(mblocks, 1), 256, SMEM_BYTES>>>(
        hbuf, W_out, b_out, out,
        nullptr, nullptr, nullptr,
        /*extra=*/wh_elec, M);
}